// round 1
// baseline (speedup 1.0000x reference)
#include <cuda_runtime.h>
#include <cuda_bf16.h>

// ---------------------------------------------------------------------------
// QuanvolutionQLSTM: conv2x2/s2 -> 196-step LSTM (B=4096, H=128, in=4) -> clf
//
// Inputs (metadata order):
//  0 x      (4096,1,28,28) f32
//  1 conv_w (4,1,2,2)      f32
//  2 conv_b (4,)           f32
//  3 Wf (128,132) 4 bf(128) 5 Wi 6 bi 7 Wg 8 bg 9 Wo 10 bo
// 11 clf_w (10,128) 12 clf_b (10,)
// Output: (4096,10) f32 log_softmax
// ---------------------------------------------------------------------------

#define BATCH   4096
#define HID     128
#define CIN     4
#define COMBK   132      // 4 + 128
#define KP      136      // padded K (multiple of 8)
#define KALLOC  140      // KP + 4 (prefetch overrun pad)
#define NSTEP   196
#define TB      32       // batch rows per CTA
#define NCTA    (BATCH / TB)   // 128
#define BLOCK   256
#define NCLS    10

// Scratch (static device arrays; no allocation in kernel_launch)
__device__ float g_Wcat[KALLOC * HID * 4];       // [k][j][gate] gate: f,i,g,o
__device__ float g_xseq[NSTEP * BATCH * CIN];    // [t][b][c]

// ---------------------------------------------------------------------------
__global__ void repack_kernel(const float* __restrict__ Wf,
                              const float* __restrict__ Wi,
                              const float* __restrict__ Wg,
                              const float* __restrict__ Wo) {
    int idx = blockIdx.x * blockDim.x + threadIdx.x;   // over KALLOC*HID
    if (idx >= KALLOC * HID) return;
    int k = idx / HID;
    int j = idx % HID;
    float4 v;
    if (k < COMBK) {
        v.x = Wf[j * COMBK + k];
        v.y = Wi[j * COMBK + k];
        v.z = Wg[j * COMBK + k];
        v.w = Wo[j * COMBK + k];
    } else {
        v = make_float4(0.f, 0.f, 0.f, 0.f);
    }
    reinterpret_cast<float4*>(g_Wcat)[idx] = v;
}

// ---------------------------------------------------------------------------
__global__ void conv_kernel(const float* __restrict__ x,
                            const float* __restrict__ cw,
                            const float* __restrict__ cb) {
    int idx = blockIdx.x * blockDim.x + threadIdx.x;   // over BATCH*196
    if (idx >= BATCH * NSTEP) return;
    int b = idx % BATCH;          // fastest -> coalesced writes
    int p = idx / BATCH;          // patch index = ph*14+pw (time step)
    int ph = p / 14, pw = p % 14;
    const float* xb = x + b * (28 * 28);
    float v00 = xb[(2 * ph) * 28 + 2 * pw];
    float v01 = xb[(2 * ph) * 28 + 2 * pw + 1];
    float v10 = xb[(2 * ph + 1) * 28 + 2 * pw];
    float v11 = xb[(2 * ph + 1) * 28 + 2 * pw + 1];
    float o[CIN];
#pragma unroll
    for (int c = 0; c < CIN; c++) {
        o[c] = cb[c] + v00 * cw[c * 4 + 0] + v01 * cw[c * 4 + 1]
                     + v10 * cw[c * 4 + 2] + v11 * cw[c * 4 + 3];
    }
    float4 ov = make_float4(o[0], o[1], o[2], o[3]);
    reinterpret_cast<float4*>(g_xseq)[p * BATCH + b] = ov;
}

// ---------------------------------------------------------------------------
__device__ __forceinline__ float sigmoidf_fast(float x) {
    x = fmaxf(fminf(x, 30.f), -30.f);
    return __fdividef(1.f, 1.f + __expf(-x));
}
__device__ __forceinline__ float tanhf_fast(float x) {
    x = fmaxf(fminf(x, 15.f), -15.f);
    float e = __expf(-2.f * x);
    return __fdividef(1.f - e, 1.f + e);
}

__global__ void __launch_bounds__(BLOCK)
lstm_kernel(const float* __restrict__ bf, const float* __restrict__ bi,
            const float* __restrict__ bgv, const float* __restrict__ bo,
            const float* __restrict__ clfw, const float* __restrict__ clfb,
            float* __restrict__ out) {
    __shared__ float comb[TB][KP];     // [b][k]: cols 0..3 = x_t, 4..131 = h
    __shared__ float slog[TB][NCLS];

    const int tid = threadIdx.x;
    const int jr  = tid & 127;         // hidden unit
    const int rg  = tid >> 7;          // row group 0/1
    const int rbase = rg * 16;
    const int row0 = blockIdx.x * TB;

    const float biasf = bf[jr];
    const float biasi = bi[jr];
    const float biasg = bgv[jr];
    const float biaso = bo[jr];

    float c[16];
#pragma unroll
    for (int b = 0; b < 16; b++) c[b] = 0.f;

    // init shared: h = 0, K-pad = 0, x(0)
#pragma unroll
    for (int b = 0; b < 16; b++) comb[rbase + b][4 + jr] = 0.f;
    if (tid < 128) {
        int b = tid >> 2, ci = tid & 3;
        comb[b][COMBK + ci] = 0.f;                                  // pad cols
        comb[b][ci] = g_xseq[(0 * BATCH + row0 + b) * 4 + ci];      // x(0)
    }

    const float4* wp = reinterpret_cast<const float4*>(g_Wcat) + jr;

    for (int t = 0; t < NSTEP; t++) {
        __syncthreads();   // comb (x_t, h_{t-1}) ready

        float accf[16], acci[16], accg[16], acco[16];
#pragma unroll
        for (int b = 0; b < 16; b++) {
            accf[b] = biasf; acci[b] = biasi; accg[b] = biasg; acco[b] = biaso;
        }

        float4 w0 = wp[0 * HID];
        float4 w1 = wp[1 * HID];
        float4 w2 = wp[2 * HID];
        float4 w3 = wp[3 * HID];

#pragma unroll 1
        for (int kk = 0; kk < KP; kk += 4) {
            // prefetch next k-group (pad rows guarantee in-bounds)
            float4 n0 = wp[(kk + 4) * HID];
            float4 n1 = wp[(kk + 5) * HID];
            float4 n2 = wp[(kk + 6) * HID];
            float4 n3 = wp[(kk + 7) * HID];
#pragma unroll
            for (int b = 0; b < 16; b++) {
                float4 cv = *reinterpret_cast<const float4*>(&comb[rbase + b][kk]);
                accf[b] = fmaf(w0.x, cv.x, accf[b]);
                acci[b] = fmaf(w0.y, cv.x, acci[b]);
                accg[b] = fmaf(w0.z, cv.x, accg[b]);
                acco[b] = fmaf(w0.w, cv.x, acco[b]);
                accf[b] = fmaf(w1.x, cv.y, accf[b]);
                acci[b] = fmaf(w1.y, cv.y, acci[b]);
                accg[b] = fmaf(w1.z, cv.y, accg[b]);
                acco[b] = fmaf(w1.w, cv.y, acco[b]);
                accf[b] = fmaf(w2.x, cv.z, accf[b]);
                acci[b] = fmaf(w2.y, cv.z, acci[b]);
                accg[b] = fmaf(w2.z, cv.z, accg[b]);
                acco[b] = fmaf(w2.w, cv.z, acco[b]);
                accf[b] = fmaf(w3.x, cv.w, accf[b]);
                acci[b] = fmaf(w3.y, cv.w, acci[b]);
                accg[b] = fmaf(w3.z, cv.w, accg[b]);
                acco[b] = fmaf(w3.w, cv.w, acco[b]);
            }
            w0 = n0; w1 = n1; w2 = n2; w3 = n3;
        }

        // elementwise LSTM update (registers only)
        float hnew[16];
#pragma unroll
        for (int b = 0; b < 16; b++) {
            float fg = sigmoidf_fast(accf[b]);
            float ig = sigmoidf_fast(acci[b]);
            float gg = tanhf_fast(accg[b]);
            float og = sigmoidf_fast(acco[b]);
            float cn = fmaf(fg, c[b], ig * gg);
            c[b] = cn;
            hnew[b] = og * tanhf_fast(cn);
        }

        __syncthreads();   // everyone done reading comb

#pragma unroll
        for (int b = 0; b < 16; b++) comb[rbase + b][4 + jr] = hnew[b];
        if (t + 1 < NSTEP && tid < 128) {
            int b = tid >> 2, ci = tid & 3;
            comb[b][ci] = g_xseq[((t + 1) * BATCH + row0 + b) * 4 + ci];
        }
    }

    __syncthreads();   // final h in comb

    // classifier: logits[b][cls] = h[b] . clf_w[cls] + clf_b[cls]
    for (int p = tid; p < TB * NCLS; p += BLOCK) {
        int b = p / NCLS, cls = p % NCLS;
        float acc = clfb[cls];
        const float* wrow = clfw + cls * HID;
#pragma unroll 4
        for (int j = 0; j < HID; j++) acc = fmaf(comb[b][4 + j], wrow[j], acc);
        slog[b][cls] = acc;
    }
    __syncthreads();

    // log_softmax per row
    if (tid < TB) {
        int b = tid;
        float m = slog[b][0];
#pragma unroll
        for (int k = 1; k < NCLS; k++) m = fmaxf(m, slog[b][k]);
        float s = 0.f;
#pragma unroll
        for (int k = 0; k < NCLS; k++) s += __expf(slog[b][k] - m);
        float lse = m + logf(s);
#pragma unroll
        for (int k = 0; k < NCLS; k++)
            out[(row0 + b) * NCLS + k] = slog[b][k] - lse;
    }
}

// ---------------------------------------------------------------------------
extern "C" void kernel_launch(void* const* d_in, const int* in_sizes, int n_in,
                              void* d_out, int out_size) {
    const float* x      = (const float*)d_in[0];
    const float* conv_w = (const float*)d_in[1];
    const float* conv_b = (const float*)d_in[2];
    const float* Wf     = (const float*)d_in[3];
    const float* bf     = (const float*)d_in[4];
    const float* Wi     = (const float*)d_in[5];
    const float* bi     = (const float*)d_in[6];
    const float* Wg     = (const float*)d_in[7];
    const float* bg     = (const float*)d_in[8];
    const float* Wo     = (const float*)d_in[9];
    const float* bo     = (const float*)d_in[10];
    const float* clf_w  = (const float*)d_in[11];
    const float* clf_b  = (const float*)d_in[12];
    float* out = (float*)d_out;

    {
        int n = KALLOC * HID;
        repack_kernel<<<(n + 255) / 256, 256>>>(Wf, Wi, Wg, Wo);
    }
    {
        int n = BATCH * NSTEP;
        conv_kernel<<<(n + 255) / 256, 256>>>(x, conv_w, conv_b);
    }
    lstm_kernel<<<NCTA, BLOCK>>>(bf, bi, bg, bo, clf_w, clf_b, out);
}

// round 2
// speedup vs baseline: 1.1407x; 1.1407x over previous
#include <cuda_runtime.h>
#include <cuda_bf16.h>

// ---------------------------------------------------------------------------
// QuanvolutionQLSTM: conv2x2/s2 -> 196-step LSTM (B=4096, H=128, in=4) -> clf
// R2: packed fma.rn.f32x2 (gate pairs fi/go in 64-bit lanes) + grid 147x28
// ---------------------------------------------------------------------------

#define BATCH   4096
#define HID     128
#define CIN     4
#define COMBK   132      // 4 + 128
#define KP      136      // padded K (multiple of 8)
#define KALLOC  140      // KP + 4 (prefetch overrun pad)
#define NSTEP   196
#define TB      28       // batch rows per CTA
#define ROWS    14       // rows per thread (TB/2)
#define NCTA    147      // ceil(4096/28)
#define BLOCK   256
#define NCLS    10

typedef unsigned long long u64;

// Scratch (static device arrays; no allocation in kernel_launch)
__device__ float g_Wcat[KALLOC * HID * 4];       // [k][j][f,i,g,o]
__device__ float g_xseq[NSTEP * BATCH * CIN];    // [t][b][c]

#define FMA2(d, a, b, c) \
    asm("fma.rn.f32x2 %0, %1, %2, %3;" : "=l"(d) : "l"(a), "l"(b), "l"(c))
#define PACK2(d, lo, hi) \
    asm("mov.b64 %0, {%1, %2};" : "=l"(d) : "f"(lo), "f"(hi))
#define UNPACK2(lo, hi, s) \
    asm("mov.b64 {%0, %1}, %2;" : "=f"(lo), "=f"(hi) : "l"(s))

// ---------------------------------------------------------------------------
__global__ void repack_kernel(const float* __restrict__ Wf,
                              const float* __restrict__ Wi,
                              const float* __restrict__ Wg,
                              const float* __restrict__ Wo) {
    int idx = blockIdx.x * blockDim.x + threadIdx.x;   // over KALLOC*HID
    if (idx >= KALLOC * HID) return;
    int k = idx / HID;
    int j = idx % HID;
    float4 v;
    if (k < COMBK) {
        v.x = Wf[j * COMBK + k];
        v.y = Wi[j * COMBK + k];
        v.z = Wg[j * COMBK + k];
        v.w = Wo[j * COMBK + k];
    } else {
        v = make_float4(0.f, 0.f, 0.f, 0.f);
    }
    reinterpret_cast<float4*>(g_Wcat)[idx] = v;
}

// ---------------------------------------------------------------------------
__global__ void conv_kernel(const float* __restrict__ x,
                            const float* __restrict__ cw,
                            const float* __restrict__ cb) {
    int idx = blockIdx.x * blockDim.x + threadIdx.x;   // over BATCH*196
    if (idx >= BATCH * NSTEP) return;
    int b = idx % BATCH;          // fastest -> coalesced writes
    int p = idx / BATCH;          // patch index = ph*14+pw (time step)
    int ph = p / 14, pw = p % 14;
    const float* xb = x + b * (28 * 28);
    float v00 = xb[(2 * ph) * 28 + 2 * pw];
    float v01 = xb[(2 * ph) * 28 + 2 * pw + 1];
    float v10 = xb[(2 * ph + 1) * 28 + 2 * pw];
    float v11 = xb[(2 * ph + 1) * 28 + 2 * pw + 1];
    float o[CIN];
#pragma unroll
    for (int c = 0; c < CIN; c++) {
        o[c] = cb[c] + v00 * cw[c * 4 + 0] + v01 * cw[c * 4 + 1]
                     + v10 * cw[c * 4 + 2] + v11 * cw[c * 4 + 3];
    }
    float4 ov = make_float4(o[0], o[1], o[2], o[3]);
    reinterpret_cast<float4*>(g_xseq)[p * BATCH + b] = ov;
}

// ---------------------------------------------------------------------------
__device__ __forceinline__ float sigmoidf_fast(float x) {
    x = fmaxf(fminf(x, 30.f), -30.f);
    return __fdividef(1.f, 1.f + __expf(-x));
}
__device__ __forceinline__ float tanhf_fast(float x) {
    x = fmaxf(fminf(x, 15.f), -15.f);
    float e = __expf(-2.f * x);
    return __fdividef(1.f - e, 1.f + e);
}

__global__ void __launch_bounds__(BLOCK)
lstm_kernel(const float* __restrict__ bf, const float* __restrict__ bi,
            const float* __restrict__ bgv, const float* __restrict__ bo,
            const float* __restrict__ clfw, const float* __restrict__ clfb,
            float* __restrict__ out) {
    // comb2[b][k] = (v, v) duplicated pair -> LDS.128 yields 2 packed operands
    __shared__ float2 comb2[TB][KP];
    __shared__ float slog[TB][NCLS];

    const int tid = threadIdx.x;
    const int jr  = tid & 127;         // hidden unit
    const int rg  = tid >> 7;          // row group 0/1
    const int rbase = rg * ROWS;
    const int row0 = blockIdx.x * TB;

    u64 bias_fi, bias_go;
    {
        float a = bf[jr], b = bi[jr], c = bgv[jr], d = bo[jr];
        PACK2(bias_fi, a, b);
        PACK2(bias_go, c, d);
    }

    float c[ROWS];
#pragma unroll
    for (int b = 0; b < ROWS; b++) c[b] = 0.f;

    // init shared: h = 0, K-pad = 0, x(0)
#pragma unroll
    for (int b = 0; b < ROWS; b++)
        comb2[rbase + b][4 + jr] = make_float2(0.f, 0.f);
    if (tid < TB * CIN) {
        int b = tid >> 2, ci = tid & 3;
        comb2[b][COMBK + ci] = make_float2(0.f, 0.f);   // pad cols
        int row = row0 + b; if (row > BATCH - 1) row = BATCH - 1;
        float v = g_xseq[(0 * BATCH + row) * 4 + ci];
        comb2[b][ci] = make_float2(v, v);
    }

    // weights: [k][j] 16B = ((f,i),(g,o)) as two u64 lanespairs
    const ulonglong2* wp = reinterpret_cast<const ulonglong2*>(g_Wcat) + jr;

    for (int t = 0; t < NSTEP; t++) {
        __syncthreads();   // comb (x_t, h_{t-1}) ready

        u64 acc_fi[ROWS], acc_go[ROWS];
#pragma unroll
        for (int b = 0; b < ROWS; b++) { acc_fi[b] = bias_fi; acc_go[b] = bias_go; }

        ulonglong2 w0 = wp[0 * HID];
        ulonglong2 w1 = wp[1 * HID];
        ulonglong2 w2 = wp[2 * HID];
        ulonglong2 w3 = wp[3 * HID];

#pragma unroll 1
        for (int kk = 0; kk < KP; kk += 4) {
            // prefetch next k-group (pad rows guarantee in-bounds)
            ulonglong2 n0 = wp[(kk + 4) * HID];
            ulonglong2 n1 = wp[(kk + 5) * HID];
            ulonglong2 n2 = wp[(kk + 6) * HID];
            ulonglong2 n3 = wp[(kk + 7) * HID];
#pragma unroll
            for (int b = 0; b < ROWS; b++) {
                const ulonglong2* cr =
                    reinterpret_cast<const ulonglong2*>(&comb2[rbase + b][kk]);
                ulonglong2 c01 = cr[0];   // (k0,k0),(k1,k1)
                ulonglong2 c23 = cr[1];   // (k2,k2),(k3,k3)
                FMA2(acc_fi[b], w0.x, c01.x, acc_fi[b]);
                FMA2(acc_go[b], w0.y, c01.x, acc_go[b]);
                FMA2(acc_fi[b], w1.x, c01.y, acc_fi[b]);
                FMA2(acc_go[b], w1.y, c01.y, acc_go[b]);
                FMA2(acc_fi[b], w2.x, c23.x, acc_fi[b]);
                FMA2(acc_go[b], w2.y, c23.x, acc_go[b]);
                FMA2(acc_fi[b], w3.x, c23.y, acc_fi[b]);
                FMA2(acc_go[b], w3.y, c23.y, acc_go[b]);
            }
            w0 = n0; w1 = n1; w2 = n2; w3 = n3;
        }

        // elementwise LSTM update (registers only)
        float hnew[ROWS];
#pragma unroll
        for (int b = 0; b < ROWS; b++) {
            float af, ai, ag, ao;
            UNPACK2(af, ai, acc_fi[b]);
            UNPACK2(ag, ao, acc_go[b]);
            float fg = sigmoidf_fast(af);
            float ig = sigmoidf_fast(ai);
            float gg = tanhf_fast(ag);
            float og = sigmoidf_fast(ao);
            float cn = fmaf(fg, c[b], ig * gg);
            c[b] = cn;
            hnew[b] = og * tanhf_fast(cn);
        }

        __syncthreads();   // everyone done reading comb

#pragma unroll
        for (int b = 0; b < ROWS; b++)
            comb2[rbase + b][4 + jr] = make_float2(hnew[b], hnew[b]);
        if (t + 1 < NSTEP && tid < TB * CIN) {
            int b = tid >> 2, ci = tid & 3;
            int row = row0 + b; if (row > BATCH - 1) row = BATCH - 1;
            float v = g_xseq[((t + 1) * BATCH + row) * 4 + ci];
            comb2[b][ci] = make_float2(v, v);
        }
    }

    __syncthreads();   // final h in comb2

    // classifier: logits[b][cls] = h[b] . clf_w[cls] + clf_b[cls]
    for (int p = tid; p < TB * NCLS; p += BLOCK) {
        int b = p / NCLS, cls = p % NCLS;
        float acc = clfb[cls];
        const float* wrow = clfw + cls * HID;
#pragma unroll 4
        for (int j = 0; j < HID; j++) acc = fmaf(comb2[b][4 + j].x, wrow[j], acc);
        slog[b][cls] = acc;
    }
    __syncthreads();

    // log_softmax per row
    if (tid < TB) {
        int b = tid;
        if (row0 + b < BATCH) {
            float m = slog[b][0];
#pragma unroll
            for (int k = 1; k < NCLS; k++) m = fmaxf(m, slog[b][k]);
            float s = 0.f;
#pragma unroll
            for (int k = 0; k < NCLS; k++) s += __expf(slog[b][k] - m);
            float lse = m + logf(s);
#pragma unroll
            for (int k = 0; k < NCLS; k++)
                out[(row0 + b) * NCLS + k] = slog[b][k] - lse;
        }
    }
}

// ---------------------------------------------------------------------------
extern "C" void kernel_launch(void* const* d_in, const int* in_sizes, int n_in,
                              void* d_out, int out_size) {
    const float* x      = (const float*)d_in[0];
    const float* conv_w = (const float*)d_in[1];
    const float* conv_b = (const float*)d_in[2];
    const float* Wf     = (const float*)d_in[3];
    const float* bf     = (const float*)d_in[4];
    const float* Wi     = (const float*)d_in[5];
    const float* bi     = (const float*)d_in[6];
    const float* Wg     = (const float*)d_in[7];
    const float* bg     = (const float*)d_in[8];
    const float* Wo     = (const float*)d_in[9];
    const float* bo     = (const float*)d_in[10];
    const float* clf_w  = (const float*)d_in[11];
    const float* clf_b  = (const float*)d_in[12];
    float* out = (float*)d_out;

    {
        int n = KALLOC * HID;
        repack_kernel<<<(n + 255) / 256, 256>>>(Wf, Wi, Wg, Wo);
    }
    {
        int n = BATCH * NSTEP;
        conv_kernel<<<(n + 255) / 256, 256>>>(x, conv_w, conv_b);
    }
    lstm_kernel<<<NCTA, BLOCK>>>(bf, bi, bg, bo, clf_w, clf_b, out);
}

// round 4
// speedup vs baseline: 1.1419x; 1.0010x over previous
#include <cuda_runtime.h>
#include <cuda_bf16.h>

// ---------------------------------------------------------------------------
// QuanvolutionQLSTM: conv2x2/s2 -> 196-step LSTM (B=4096, H=128, in=4) -> clf
// R2: packed fma.rn.f32x2 (gate pairs fi/go in 64-bit lanes) + grid 147x28
// ---------------------------------------------------------------------------

#define BATCH   4096
#define HID     128
#define CIN     4
#define COMBK   132      // 4 + 128
#define KP      136      // padded K (multiple of 8)
#define KALLOC  140      // KP + 4 (prefetch overrun pad)
#define NSTEP   196
#define TB      28       // batch rows per CTA
#define ROWS    14       // rows per thread (TB/2)
#define NCTA    147      // ceil(4096/28)
#define BLOCK   256
#define NCLS    10

typedef unsigned long long u64;

// Scratch (static device arrays; no allocation in kernel_launch)
__device__ float g_Wcat[KALLOC * HID * 4];       // [k][j][f,i,g,o]
__device__ float g_xseq[NSTEP * BATCH * CIN];    // [t][b][c]

#define FMA2(d, a, b, c) \
    asm("fma.rn.f32x2 %0, %1, %2, %3;" : "=l"(d) : "l"(a), "l"(b), "l"(c))
#define PACK2(d, lo, hi) \
    asm("mov.b64 %0, {%1, %2};" : "=l"(d) : "f"(lo), "f"(hi))
#define UNPACK2(lo, hi, s) \
    asm("mov.b64 {%0, %1}, %2;" : "=f"(lo), "=f"(hi) : "l"(s))

// ---------------------------------------------------------------------------
__global__ void repack_kernel(const float* __restrict__ Wf,
                              const float* __restrict__ Wi,
                              const float* __restrict__ Wg,
                              const float* __restrict__ Wo) {
    int idx = blockIdx.x * blockDim.x + threadIdx.x;   // over KALLOC*HID
    if (idx >= KALLOC * HID) return;
    int k = idx / HID;
    int j = idx % HID;
    float4 v;
    if (k < COMBK) {
        v.x = Wf[j * COMBK + k];
        v.y = Wi[j * COMBK + k];
        v.z = Wg[j * COMBK + k];
        v.w = Wo[j * COMBK + k];
    } else {
        v = make_float4(0.f, 0.f, 0.f, 0.f);
    }
    reinterpret_cast<float4*>(g_Wcat)[idx] = v;
}

// ---------------------------------------------------------------------------
__global__ void conv_kernel(const float* __restrict__ x,
                            const float* __restrict__ cw,
                            const float* __restrict__ cb) {
    int idx = blockIdx.x * blockDim.x + threadIdx.x;   // over BATCH*196
    if (idx >= BATCH * NSTEP) return;
    int b = idx % BATCH;          // fastest -> coalesced writes
    int p = idx / BATCH;          // patch index = ph*14+pw (time step)
    int ph = p / 14, pw = p % 14;
    const float* xb = x + b * (28 * 28);
    float v00 = xb[(2 * ph) * 28 + 2 * pw];
    float v01 = xb[(2 * ph) * 28 + 2 * pw + 1];
    float v10 = xb[(2 * ph + 1) * 28 + 2 * pw];
    float v11 = xb[(2 * ph + 1) * 28 + 2 * pw + 1];
    float o[CIN];
#pragma unroll
    for (int c = 0; c < CIN; c++) {
        o[c] = cb[c] + v00 * cw[c * 4 + 0] + v01 * cw[c * 4 + 1]
                     + v10 * cw[c * 4 + 2] + v11 * cw[c * 4 + 3];
    }
    float4 ov = make_float4(o[0], o[1], o[2], o[3]);
    reinterpret_cast<float4*>(g_xseq)[p * BATCH + b] = ov;
}

// ---------------------------------------------------------------------------
__device__ __forceinline__ float sigmoidf_fast(float x) {
    x = fmaxf(fminf(x, 30.f), -30.f);
    return __fdividef(1.f, 1.f + __expf(-x));
}
__device__ __forceinline__ float tanhf_fast(float x) {
    x = fmaxf(fminf(x, 15.f), -15.f);
    float e = __expf(-2.f * x);
    return __fdividef(1.f - e, 1.f + e);
}

__global__ void __launch_bounds__(BLOCK)
lstm_kernel(const float* __restrict__ bf, const float* __restrict__ bi,
            const float* __restrict__ bgv, const float* __restrict__ bo,
            const float* __restrict__ clfw, const float* __restrict__ clfb,
            float* __restrict__ out) {
    // comb2[b][k] = (v, v) duplicated pair -> LDS.128 yields 2 packed operands
    __shared__ float2 comb2[TB][KP];
    __shared__ float slog[TB][NCLS];

    const int tid = threadIdx.x;
    const int jr  = tid & 127;         // hidden unit
    const int rg  = tid >> 7;          // row group 0/1
    const int rbase = rg * ROWS;
    const int row0 = blockIdx.x * TB;

    u64 bias_fi, bias_go;
    {
        float a = bf[jr], b = bi[jr], c = bgv[jr], d = bo[jr];
        PACK2(bias_fi, a, b);
        PACK2(bias_go, c, d);
    }

    float c[ROWS];
#pragma unroll
    for (int b = 0; b < ROWS; b++) c[b] = 0.f;

    // init shared: h = 0, K-pad = 0, x(0)
#pragma unroll
    for (int b = 0; b < ROWS; b++)
        comb2[rbase + b][4 + jr] = make_float2(0.f, 0.f);
    if (tid < TB * CIN) {
        int b = tid >> 2, ci = tid & 3;
        comb2[b][COMBK + ci] = make_float2(0.f, 0.f);   // pad cols
        int row = row0 + b; if (row > BATCH - 1) row = BATCH - 1;
        float v = g_xseq[(0 * BATCH + row) * 4 + ci];
        comb2[b][ci] = make_float2(v, v);
    }

    // weights: [k][j] 16B = ((f,i),(g,o)) as two u64 lanespairs
    const ulonglong2* wp = reinterpret_cast<const ulonglong2*>(g_Wcat) + jr;

    for (int t = 0; t < NSTEP; t++) {
        __syncthreads();   // comb (x_t, h_{t-1}) ready

        u64 acc_fi[ROWS], acc_go[ROWS];
#pragma unroll
        for (int b = 0; b < ROWS; b++) { acc_fi[b] = bias_fi; acc_go[b] = bias_go; }

        ulonglong2 w0 = wp[0 * HID];
        ulonglong2 w1 = wp[1 * HID];
        ulonglong2 w2 = wp[2 * HID];
        ulonglong2 w3 = wp[3 * HID];

#pragma unroll 1
        for (int kk = 0; kk < KP; kk += 4) {
            // prefetch next k-group (pad rows guarantee in-bounds)
            ulonglong2 n0 = wp[(kk + 4) * HID];
            ulonglong2 n1 = wp[(kk + 5) * HID];
            ulonglong2 n2 = wp[(kk + 6) * HID];
            ulonglong2 n3 = wp[(kk + 7) * HID];
#pragma unroll
            for (int b = 0; b < ROWS; b++) {
                const ulonglong2* cr =
                    reinterpret_cast<const ulonglong2*>(&comb2[rbase + b][kk]);
                ulonglong2 c01 = cr[0];   // (k0,k0),(k1,k1)
                ulonglong2 c23 = cr[1];   // (k2,k2),(k3,k3)
                FMA2(acc_fi[b], w0.x, c01.x, acc_fi[b]);
                FMA2(acc_go[b], w0.y, c01.x, acc_go[b]);
                FMA2(acc_fi[b], w1.x, c01.y, acc_fi[b]);
                FMA2(acc_go[b], w1.y, c01.y, acc_go[b]);
                FMA2(acc_fi[b], w2.x, c23.x, acc_fi[b]);
                FMA2(acc_go[b], w2.y, c23.x, acc_go[b]);
                FMA2(acc_fi[b], w3.x, c23.y, acc_fi[b]);
                FMA2(acc_go[b], w3.y, c23.y, acc_go[b]);
            }
            w0 = n0; w1 = n1; w2 = n2; w3 = n3;
        }

        // elementwise LSTM update (registers only)
        float hnew[ROWS];
#pragma unroll
        for (int b = 0; b < ROWS; b++) {
            float af, ai, ag, ao;
            UNPACK2(af, ai, acc_fi[b]);
            UNPACK2(ag, ao, acc_go[b]);
            float fg = sigmoidf_fast(af);
            float ig = sigmoidf_fast(ai);
            float gg = tanhf_fast(ag);
            float og = sigmoidf_fast(ao);
            float cn = fmaf(fg, c[b], ig * gg);
            c[b] = cn;
            hnew[b] = og * tanhf_fast(cn);
        }

        __syncthreads();   // everyone done reading comb

#pragma unroll
        for (int b = 0; b < ROWS; b++)
            comb2[rbase + b][4 + jr] = make_float2(hnew[b], hnew[b]);
        if (t + 1 < NSTEP && tid < TB * CIN) {
            int b = tid >> 2, ci = tid & 3;
            int row = row0 + b; if (row > BATCH - 1) row = BATCH - 1;
            float v = g_xseq[((t + 1) * BATCH + row) * 4 + ci];
            comb2[b][ci] = make_float2(v, v);
        }
    }

    __syncthreads();   // final h in comb2

    // classifier: logits[b][cls] = h[b] . clf_w[cls] + clf_b[cls]
    for (int p = tid; p < TB * NCLS; p += BLOCK) {
        int b = p / NCLS, cls = p % NCLS;
        float acc = clfb[cls];
        const float* wrow = clfw + cls * HID;
#pragma unroll 4
        for (int j = 0; j < HID; j++) acc = fmaf(comb2[b][4 + j].x, wrow[j], acc);
        slog[b][cls] = acc;
    }
    __syncthreads();

    // log_softmax per row
    if (tid < TB) {
        int b = tid;
        if (row0 + b < BATCH) {
            float m = slog[b][0];
#pragma unroll
            for (int k = 1; k < NCLS; k++) m = fmaxf(m, slog[b][k]);
            float s = 0.f;
#pragma unroll
            for (int k = 0; k < NCLS; k++) s += __expf(slog[b][k] - m);
            float lse = m + logf(s);
#pragma unroll
            for (int k = 0; k < NCLS; k++)
                out[(row0 + b) * NCLS + k] = slog[b][k] - lse;
        }
    }
}

// ---------------------------------------------------------------------------
extern "C" void kernel_launch(void* const* d_in, const int* in_sizes, int n_in,
                              void* d_out, int out_size) {
    const float* x      = (const float*)d_in[0];
    const float* conv_w = (const float*)d_in[1];
    const float* conv_b = (const float*)d_in[2];
    const float* Wf     = (const float*)d_in[3];
    const float* bf     = (const float*)d_in[4];
    const float* Wi     = (const float*)d_in[5];
    const float* bi     = (const float*)d_in[6];
    const float* Wg     = (const float*)d_in[7];
    const float* bg     = (const float*)d_in[8];
    const float* Wo     = (const float*)d_in[9];
    const float* bo     = (const float*)d_in[10];
    const float* clf_w  = (const float*)d_in[11];
    const float* clf_b  = (const float*)d_in[12];
    float* out = (float*)d_out;

    {
        int n = KALLOC * HID;
        repack_kernel<<<(n + 255) / 256, 256>>>(Wf, Wi, Wg, Wo);
    }
    {
        int n = BATCH * NSTEP;
        conv_kernel<<<(n + 255) / 256, 256>>>(x, conv_w, conv_b);
    }
    lstm_kernel<<<NCTA, BLOCK>>>(bf, bi, bg, bo, clf_w, clf_b, out);
}